// round 1
// baseline (speedup 1.0000x reference)
#include <cuda_runtime.h>

// PLNet expansion: out[pp][n,k,i,j,y,x] =
//   0.5*cor0[ij]*cork[ij] * cen0[yx]*cenk[yx]
//   * cor[23+y][ij] * cor[37+x][ij] * cen[23+i][yx] * cen[37+j][yx]
// cor = corner(pp&1), cen = center(pp>>1).
// Input layout (n, 204, 14, 14): corner1 ch 0..50, corner2 51..101,
// center1 102..152, center2 153..203.
//
// Block (k=bx, n=by, ichunk=bz covers i in {2bz, 2bz+1}), 196 threads.
// Thread t: pp = t/49 (which output tensor), q = t%49 (float4 quad in the
// 196-element (y,x) plane). Stores are aligned float4, fully coalesced.

__global__ __launch_bounds__(196)
void plnet_kernel(const float* __restrict__ in, float* __restrict__ out)
{
    const int k  = blockIdx.x;   // 0..19
    const int n  = blockIdx.y;   // 0..31
    const int i0 = blockIdx.z * 2;  // i chunk start (0,2,...,12)
    const int t  = threadIdx.x;

    // W[cc][rij][y] = 0.5*cor0*cork*cor[23+y] at ij = i0*14+rij  (rij 0..27)
    // V[cc][rij][x] = cor[37+x] at same ij
    __shared__ float W_s[2 * 28 * 14];
    __shared__ float V_s[2 * 28 * 14];
    __shared__ float a_s[2 * 28];

    const float* nb = in + n * (204 * 196);

    // ---- precompute a (2 cor x 28 ij rows) ----
    if (t < 56) {
        const int cc  = t / 28;
        const int rij = t - cc * 28;
        const int ij  = i0 * 14 + rij;
        const float* cor = nb + cc * (51 * 196);
        a_s[t] = 0.5f * cor[ij] * cor[(1 + k) * 196 + ij];
    }
    __syncthreads();

    // ---- fill W,V (coalesced gmem reads: rij fastest) ----
    #pragma unroll
    for (int idx = 0; idx < 784; idx += 196) {
        const int id  = idx + t;
        const int rij = id % 28;
        const int tmp = id / 28;        // 0..27
        const int y   = tmp % 14;
        const int cc  = tmp / 14;
        const int ij  = i0 * 14 + rij;
        const float* cor = nb + cc * (51 * 196);
        W_s[cc * 392 + rij * 14 + y] = a_s[cc * 28 + rij] * cor[(23 + y) * 196 + ij];
        V_s[cc * 392 + rij * 14 + y] = cor[(37 + y) * 196 + ij];
    }

    // ---- per-thread setup ----
    const int pp = t / 49;          // output tensor 0..3
    const int q  = t - pp * 49;     // quad index in plane
    const int cc = pp & 1;          // corner select
    const int ss = pp >> 1;         // center select
    const int e0 = q * 4;           // plane linear element base (y*14+x)
    const int y0 = e0 / 14;
    const int x0 = e0 - y0 * 14;    // even, <=12

    const float* cen = nb + (102 + ss * 51) * 196;

    // b[e] = cen0*cenk at plane elements e0..e0+3 (aligned float4: 196*4 and 16q both 16B mult)
    const float4 c0 = *(const float4*)(cen + e0);
    const float4 ck = *(const float4*)(cen + (1 + k) * 196 + e0);
    const float bx = c0.x * ck.x, by = c0.y * ck.y, bz = c0.z * ck.z, bw = c0.w * ck.w;

    // per-element x offsets / row-cross flags (only x0==12 crosses into y0+1)
    int xo1 = x0 + 1, xo2 = x0 + 2, xo3 = x0 + 3;
    const bool h1 = (xo1 >= 14), h2 = (xo2 >= 14), h3 = (xo3 >= 14);
    if (h1) xo1 -= 14;
    if (h2) xo2 -= 14;
    if (h3) xo3 -= 14;
    const int y1 = (x0 > 10) ? (y0 + 1) : y0;

    __syncthreads();

    float* op = out + (size_t)((pp * 32 + n) * 20 + k) * 38416
                    + (size_t)i0 * (14 * 196) + e0;
    const float* Wc = W_s + cc * 392;
    const float* Vc = V_s + cc * 392;

    // j in two halves of 7 so Lsy register cache stays at 28 regs
    #pragma unroll
    for (int jb = 0; jb < 14; jb += 7) {
        float4 L[7];
        #pragma unroll
        for (int j = 0; j < 7; ++j)
            L[j] = *(const float4*)(cen + (37 + jb + j) * 196 + e0);

        #pragma unroll
        for (int il = 0; il < 2; ++il) {
            const int i = i0 + il;
            const float4 sx = *(const float4*)(cen + (23 + i) * 196 + e0);
            const float r0 = bx * sx.x, r1 = by * sx.y, r2 = bz * sx.z, r3 = bw * sx.w;

            const float* Wr = Wc + il * 196;   // (il*14 + j)*14
            const float* Vr = Vc + il * 196;
            float* orow = op + (size_t)il * (14 * 196) + (size_t)jb * 196;

            #pragma unroll
            for (int j = 0; j < 7; ++j) {
                const float* wr = Wr + (jb + j) * 14;
                const float* vr = Vr + (jb + j) * 14;
                const float wlo = wr[y0];
                const float whi = wr[y1];
                float4 o;
                o.x = (wlo * vr[x0])              * (r0 * L[j].x);
                o.y = ((h1 ? whi : wlo) * vr[xo1]) * (r1 * L[j].y);
                o.z = ((h2 ? whi : wlo) * vr[xo2]) * (r2 * L[j].z);
                o.w = ((h3 ? whi : wlo) * vr[xo3]) * (r3 * L[j].w);
                *(float4*)(orow + j * 196) = o;
            }
        }
    }
}

extern "C" void kernel_launch(void* const* d_in, const int* in_sizes, int n_in,
                              void* d_out, int out_size)
{
    const float* in = (const float*)d_in[0];
    float* out = (float*)d_out;
    dim3 grid(20, 32, 7);
    plnet_kernel<<<grid, 196>>>(in, out);
}